// round 11
// baseline (speedup 1.0000x reference)
#include <cuda_runtime.h>
#include <math.h>
#include <stdint.h>

#define Nn   16
#define Pp   866
#define CIN  1280
#define Cc   512
#define HWs  64
#define NOUT 10
#define PW   5130          // (Cc+1)*NOUT
#define BN_EPS 0.001f

typedef unsigned long long ull;
typedef unsigned int uint32;

__device__ __align__(16) float g_f[Nn * Cc * HWs];

// ---------- f32x2 helpers (conv kernel) ----------
__device__ __forceinline__ ull splat2(float x) {
    ull r; asm("mov.b64 %0, {%1, %1};" : "=l"(r) : "f"(x)); return r;
}
__device__ __forceinline__ void fma2(ull &d, ull a, ull b) {
    asm("fma.rn.f32x2 %0, %1, %2, %0;" : "+l"(d) : "l"(a), "l"(b));
}
__device__ __forceinline__ float2 unpack2(ull u) {
    float2 f; asm("mov.b64 {%0, %1}, %2;" : "=f"(f.x), "=f"(f.y) : "l"(u)); return f;
}
__device__ __forceinline__ void cp16(void* dst, const void* src) {
    uint32 d = (uint32)__cvta_generic_to_shared(dst);
    asm volatile("cp.async.cg.shared.global [%0], [%1], 16;" :: "r"(d), "l"(src));
}
#define CP_COMMIT() asm volatile("cp.async.commit_group;")
#define CP_WAIT0()  asm volatile("cp.async.wait_group 0;")
#define CP_WAIT1()  asm volatile("cp.async.wait_group 1;")
#define CP_WAIT2()  asm volatile("cp.async.wait_group 2;")

// ---------- tf32 mma ----------
__device__ __forceinline__ void mma_tf32(float* d, uint32 a0, uint32 a1,
                                         uint32 a2, uint32 a3,
                                         uint32 b0, uint32 b1) {
    asm volatile(
        "mma.sync.aligned.m16n8k8.row.col.f32.tf32.tf32.f32 "
        "{%0,%1,%2,%3}, {%4,%5,%6,%7}, {%8,%9}, {%0,%1,%2,%3};"
        : "+f"(d[0]), "+f"(d[1]), "+f"(d[2]), "+f"(d[3])
        : "r"(a0), "r"(a1), "r"(a2), "r"(a3), "r"(b0), "r"(b1));
}
__device__ __forceinline__ uint32 fbits(float x) {
    uint32 r; asm("mov.b32 %0, %1;" : "=r"(r) : "f"(x)); return r;
}

// ---------- warp reductions ----------
__device__ __forceinline__ float wmax(float v) {
    #pragma unroll
    for (int o = 16; o > 0; o >>= 1)
        v = fmaxf(v, __shfl_xor_sync(0xffffffffu, v, o));
    return v;
}
__device__ __forceinline__ float wsum(float v) {
    #pragma unroll
    for (int o = 16; o > 0; o >>= 1)
        v += __shfl_xor_sync(0xffffffffu, v, o);
    return v;
}

// =====================================================================
// Kernel 1: conv 1x1 + BN + SiLU  ->  g_f[n][c][hw]
// grid (8, 16), 512 threads = 32 hw-pairs x 16 cgroups (4c each).
// 16 warps/SM. W reg-staged transpose; F cp.async double-buffer.
// =====================================================================
__global__ void __launch_bounds__(512)
conv_kernel(const float* __restrict__ feat,
            const float* __restrict__ convw,
            const float* __restrict__ gamma,
            const float* __restrict__ beta,
            const float* __restrict__ mean,
            const float* __restrict__ var)
{
    const int n  = blockIdx.y;
    const int cb = blockIdx.x * 64;
    const int t  = threadIdx.x;
    const int cs  = t & 31;      // hw pair: hw = cs*2
    const int csl = t >> 5;      // 0..15 : channels cb + csl*4 ..

    __shared__ __align__(16) float sW[32 * 64];      // [k][c]
    __shared__ __align__(16) float sF[2][32 * 64];   // [k][hw] double buffer

    ull acc[2][2];
    acc[0][0] = acc[0][1] = acc[1][0] = acc[1][1] = 0ull;

    const int stc = t >> 3;                     // staging: c index 0..63
    const int stq = t & 7;                      // staging: 4-k group
    const float* wsrc = convw + (size_t)(cb + stc) * CIN + stq * 4;
    const float* fsrc = feat + (size_t)n * CIN * HWs;

    float4 R0 = __ldg((const float4*)wsrc);

    // prologue: f chunk 0 (2048 floats, 512 cp16)
    cp16(&sF[0][t * 4], fsrc + t * 4);
    CP_COMMIT();

    int buf = 0;
    const int NCH = CIN / 32;                   // 40
    for (int ch = 0; ch < NCH; ch++) {
        const int kb = ch * 32;
        {
            int k0 = stq * 4;
            sW[(k0 + 0) * 64 + stc] = R0.x;
            sW[(k0 + 1) * 64 + stc] = R0.y;
            sW[(k0 + 2) * 64 + stc] = R0.z;
            sW[(k0 + 3) * 64 + stc] = R0.w;
        }
        if (ch + 1 < NCH) {
            cp16(&sF[buf ^ 1][t * 4], fsrc + (kb + 32) * HWs + t * 4);
            CP_COMMIT();
            CP_WAIT1();
        } else {
            CP_WAIT0();
        }
        __syncthreads();
        if (ch + 1 < NCH)
            R0 = __ldg((const float4*)(wsrc + kb + 32));

        const float* sfb = &sF[buf][cs * 2];
        #pragma unroll 8
        for (int kk = 0; kk < 32; kk++) {
            float2 bv = *(const float2*)(sfb + kk * 64);
            ull s0 = splat2(bv.x);
            ull s1 = splat2(bv.y);
            const float* wr = sW + kk * 64 + csl * 4;
            ulonglong2 w01 = *(const ulonglong2*)(wr);
            fma2(acc[0][0], w01.x, s0); fma2(acc[0][1], w01.x, s1);
            fma2(acc[1][0], w01.y, s0); fma2(acc[1][1], w01.y, s1);
        }
        __syncthreads();
        buf ^= 1;
    }

    // epilogue: BN + SiLU
    #pragma unroll
    for (int i2 = 0; i2 < 2; i2++) {
        int c0 = cb + csl * 4 + 2 * i2;
        float sc0 = __ldg(gamma + c0) * rsqrtf(__ldg(var + c0) + BN_EPS);
        float bi0 = __ldg(beta + c0) - __ldg(mean + c0) * sc0;
        float sc1 = __ldg(gamma + c0 + 1) * rsqrtf(__ldg(var + c0 + 1) + BN_EPS);
        float bi1 = __ldg(beta + c0 + 1) - __ldg(mean + c0 + 1) * sc1;
        float2 v0 = unpack2(acc[i2][0]);   // hw = cs*2   (c0 in .x, c0+1 in .y)
        float2 v1 = unpack2(acc[i2][1]);   // hw = cs*2+1
        float a00 = v0.x * sc0 + bi0;  a00 = a00 / (1.0f + __expf(-a00));
        float a01 = v1.x * sc0 + bi0;  a01 = a01 / (1.0f + __expf(-a01));
        float a10 = v0.y * sc1 + bi1;  a10 = a10 / (1.0f + __expf(-a10));
        float a11 = v1.y * sc1 + bi1;  a11 = a11 / (1.0f + __expf(-a11));
        float2* o0 = (float2*)(g_f + ((size_t)n * Cc + c0) * HWs + cs * 2);
        float2* o1 = (float2*)(g_f + ((size_t)n * Cc + c0 + 1) * HWs + cs * 2);
        *o0 = make_float2(a00, a01);
        *o1 = make_float2(a10, a11);
    }
}

// =====================================================================
// Kernel 2: head via tf32 mma.sync, 3-stage cp.async pipeline
// grid (55, 16) = 880 blocks, 320 threads = 10 warps, 16 p per block.
// M = 160 rows (row = pl*10 + j), warp w owns m16 tile w.
// N = 64 hw, K = 512 (16 chunks of 32), THREE buffers: 2 loads in flight.
// A smem: [pl][k][j], 12 floats/k-row, 388 floats/pl.
// B smem: [k][hw] stride 72 (conflict-free fragment loads).
// =====================================================================
#define PT16  16
#define NPT   55
#define KC    32
#define NKCH  16
#define SA_F  6208               // 16 * 388
#define SF_F  (KC * 72)          // 2304
#define STG_F (SA_F + SF_F)      // 8512 floats per stage
#define SMEMH_BYTES (3 * STG_F * 4)   // 102144

__global__ void __launch_bounds__(320, 2)
head_mma_kernel(const float* __restrict__ weights, float* __restrict__ out)
{
    const int n    = blockIdx.y;
    const int p0   = blockIdx.x * PT16;
    const int t    = threadIdx.x;
    const int warp = t >> 5;
    const int lane = t & 31;
    const int r4   = lane >> 2;     // 0..7
    const int c4   = lane & 3;      // 0..3

    extern __shared__ __align__(16) float smem[];
    // stage s at [s*STG_F, s*STG_F + SA_F) = A, then SF_F floats of B

    const uint32 sbase = (uint32)__cvta_generic_to_shared(smem);
    const uint32 STG_B = STG_F * 4;
    const float* gfn = g_f + (size_t)n * Cc * HWs;

    // ---- A staging: 16 pl x 160 f2 per chunk = 2560 cp8 / 320 thr = 8 each ----
    const float2* srcA[8];
    uint32 dstA[8];               // byte offset within a stage
    #pragma unroll
    for (int i = 0; i < 8; i++) {
        int idx = t + 320 * i;                 // 0..2559
        int pl  = idx / 160;
        int r   = idx - pl * 160;
        int p   = p0 + pl; if (p >= Pp) p = Pp - 1;
        srcA[i] = (const float2*)(weights + (size_t)(n * Pp + p) * PW) + r;
        dstA[i] = sbase + (uint32)(pl * 194 + r + r / 5) * 8;
    }

    // B staging: idx < 512: k = idx>>4, off = idx&15 (cp16 of 4 floats)
    // (captured in a lambda-free macro-ish block below)

    // ---- prologue: chunks 0 and 1 ----
    #pragma unroll
    for (int pc = 0; pc < 2; pc++) {
        uint32 bb = pc * STG_B;
        #pragma unroll
        for (int i = 0; i < 8; i++)
            asm volatile("cp.async.ca.shared.global [%0], [%1], 8;"
                         :: "r"(dstA[i] + bb), "l"(srcA[i] + pc * 160) : "memory");
        #pragma unroll
        for (int i = 0; i < 2; i++) {
            int idx = t + 320 * i;
            if (idx < 512) {
                int k = idx >> 4, off = idx & 15;
                uint32 d = sbase + bb + (uint32)(SA_F + k * 72 + off * 4) * 4;
                asm volatile("cp.async.cg.shared.global [%0], [%1], 16;"
                             :: "r"(d), "l"(gfn + (pc * KC + k) * 64 + off * 4)
                             : "memory");
            }
        }
        CP_COMMIT();
    }

    // ---- A frag base offsets (float indices within stage) ----
    const int m_lo = warp * 16 + r4;
    const int m_hi = m_lo + 8;
    const int pl_lo = m_lo / 10, j_lo = m_lo - pl_lo * 10;
    const int pl_hi = m_hi / 10, j_hi = m_hi - pl_hi * 10;
    const int aoff_lo = pl_lo * 388 + j_lo + c4 * 12;
    const int aoff_hi = pl_hi * 388 + j_hi + c4 * 12;
    const int boff = SA_F + c4 * 72 + r4;

    float d[8][4];
    #pragma unroll
    for (int tt = 0; tt < 8; tt++)
        #pragma unroll
        for (int k = 0; k < 4; k++) d[tt][k] = 0.0f;

    for (int ch = 0; ch < NKCH; ch++) {
        if (ch + 2 < NKCH) {
            // issue chunk ch+2 into stage (ch+2)%3
            int nc = ch + 2;
            uint32 bb = (uint32)(nc % 3) * STG_B;
            #pragma unroll
            for (int i = 0; i < 8; i++)
                asm volatile("cp.async.ca.shared.global [%0], [%1], 8;"
                             :: "r"(dstA[i] + bb), "l"(srcA[i] + nc * 160) : "memory");
            #pragma unroll
            for (int i = 0; i < 2; i++) {
                int idx = t + 320 * i;
                if (idx < 512) {
                    int k = idx >> 4, off = idx & 15;
                    uint32 dd = sbase + bb + (uint32)(SA_F + k * 72 + off * 4) * 4;
                    asm volatile("cp.async.cg.shared.global [%0], [%1], 16;"
                                 :: "r"(dd), "l"(gfn + (nc * KC + k) * 64 + off * 4)
                                 : "memory");
                }
            }
            CP_COMMIT();
            CP_WAIT2();
        } else if (ch + 1 < NKCH) {
            CP_WAIT1();
        } else {
            CP_WAIT0();
        }
        __syncthreads();

        const float* S = smem + (ch % 3) * STG_F;
        #pragma unroll
        for (int s = 0; s < 4; s++) {
            uint32 a0 = fbits(S[aoff_lo + s * 96]);
            uint32 a1 = fbits(S[aoff_hi + s * 96]);
            uint32 a2 = fbits(S[aoff_lo + s * 96 + 48]);
            uint32 a3 = fbits(S[aoff_hi + s * 96 + 48]);
            const float* Bs = S + boff + s * 576;
            #pragma unroll
            for (int tt = 0; tt < 8; tt++) {
                uint32 b0 = fbits(Bs[tt * 8]);
                uint32 b1 = fbits(Bs[tt * 8 + 288]);
                mma_tf32(d[tt], a0, a1, a2, a3, b0, b1);
            }
        }
        __syncthreads();
    }

    // ---- dump logits to smem: L[m][hw], stride 68 ----
    float* L = smem;
    #pragma unroll
    for (int tt = 0; tt < 8; tt++) {
        int col = tt * 8 + c4 * 2;
        *(float2*)(L + m_lo * 68 + col) = make_float2(d[tt][0], d[tt][1]);
        *(float2*)(L + m_hi * 68 + col) = make_float2(d[tt][2], d[tt][3]);
    }
    __syncthreads();

    // ---- epilogue: warps 0..7, each handles pl = warp and warp+8 ----
    if (warp < 8) {
        const float inv7 = 1.0f / 7.0f;
        const int hw0 = lane * 2;
        const float x0 = (float)(hw0 & 7) * inv7;
        const float x1 = (float)((hw0 + 1) & 7) * inv7;
        const float yv = (float)(hw0 >> 3) * inv7;

        #pragma unroll
        for (int rep = 0; rep < 2; rep++) {
            const int pl = warp + rep * 8;
            const int pv = p0 + pl;
            const int p  = (pv < Pp) ? pv : (Pp - 1);

            float bias = 0.0f;
            if (lane < 10)
                bias = __ldg(weights + (size_t)(n * Pp + p) * PW + Cc * NOUT + lane);

            float l[10][2];
            #pragma unroll
            for (int j = 0; j < 10; j++) {
                float2 v = *(const float2*)(L + (pl * 10 + j) * 68 + hw0);
                float bj = __shfl_sync(0xffffffffu, bias, j);
                l[j][0] = v.x + bj;
                l[j][1] = v.y + bj;
            }

            // xy softmax (channel 1)
            float mx = wmax(fmaxf(l[1][0], l[1][1]));
            float e0 = __expf(l[1][0] - mx);
            float e1 = __expf(l[1][1] - mx);
            float s  = wsum(e0 + e1);
            float sx = wsum(e0 * x0 + e1 * x1);
            float sy = wsum((e0 + e1) * yv);
            float cx = sx / s;
            float cy = sy / s;

            // 2.5D softmax (channels 2..9)
            float m2 = -INFINITY;
            #pragma unroll
            for (int j = 2; j < 10; j++)
                m2 = fmaxf(m2, fmaxf(l[j][0], l[j][1]));
            m2 = wmax(m2);

            float se = 0.0f, sx2 = 0.0f, sy2 = 0.0f, sz = 0.0f, su = 0.0f;
            #pragma unroll
            for (int j = 2; j < 10; j++) {
                float ea = __expf(l[j][0] - m2);
                float eb = __expf(l[j][1] - m2);
                float zs = (float)(j - 2) * inv7;
                se  += ea + eb;
                sx2 += ea * x0 + eb * x1;
                sy2 += (ea + eb) * yv;
                sz  += (ea + eb) * zs;
                su  += ea * l[0][0] + eb * l[0][1];
            }
            se  = wsum(se);
            sx2 = wsum(sx2);
            sy2 = wsum(sy2);
            sz  = wsum(sz);
            su  = wsum(su);

            if (lane == 0 && pv < Pp) {
                float X = sx2 / se, Y = sy2 / se, Z = sz / se, U = su / se;
                float up = fmaxf(U, 0.0f) + log1pf(__expf(-fabsf(U)));
                int gp = n * Pp + pv;
                out[gp * 2 + 0] = X;
                out[gp * 2 + 1] = Y;
                out[Nn * Pp * 2 + gp * 3 + 0] = cx;
                out[Nn * Pp * 2 + gp * 3 + 1] = cy;
                out[Nn * Pp * 2 + gp * 3 + 2] = Z;
                out[Nn * Pp * 5 + gp] = up;
            }
        }
    }
}

// =====================================================================
extern "C" void kernel_launch(void* const* d_in, const int* in_sizes, int n_in,
                              void* d_out, int out_size)
{
    const float* features = (const float*)d_in[0];
    const float* weights  = (const float*)d_in[1];
    const float* conv_w   = (const float*)d_in[2];
    const float* gamma    = (const float*)d_in[3];
    const float* beta     = (const float*)d_in[4];
    const float* mean     = (const float*)d_in[5];
    const float* var      = (const float*)d_in[6];
    float* out = (float*)d_out;

    conv_kernel<<<dim3(8, Nn), 512>>>(features, conv_w, gamma, beta, mean, var);

    cudaFuncSetAttribute(head_mma_kernel,
                         cudaFuncAttributeMaxDynamicSharedMemorySize,
                         SMEMH_BYTES);
    head_mma_kernel<<<dim3(NPT, Nn), 320, SMEMH_BYTES>>>(weights, out);
}

// round 12
// speedup vs baseline: 1.1589x; 1.1589x over previous
#include <cuda_runtime.h>
#include <math.h>
#include <stdint.h>

#define Nn   16
#define Pp   866
#define CIN  1280
#define Cc   512
#define HWs  64
#define NOUT 10
#define PW   5130          // (Cc+1)*NOUT
#define BN_EPS 0.001f

typedef unsigned long long ull;
typedef unsigned int uint32;

__device__ __align__(16) float g_f[Nn * Cc * HWs];

// ---------- f32x2 helpers (conv kernel) ----------
__device__ __forceinline__ ull splat2(float x) {
    ull r; asm("mov.b64 %0, {%1, %1};" : "=l"(r) : "f"(x)); return r;
}
__device__ __forceinline__ void fma2(ull &d, ull a, ull b) {
    asm("fma.rn.f32x2 %0, %1, %2, %0;" : "+l"(d) : "l"(a), "l"(b));
}
__device__ __forceinline__ float2 unpack2(ull u) {
    float2 f; asm("mov.b64 {%0, %1}, %2;" : "=f"(f.x), "=f"(f.y) : "l"(u)); return f;
}
__device__ __forceinline__ void cp16(void* dst, const void* src) {
    uint32 d = (uint32)__cvta_generic_to_shared(dst);
    asm volatile("cp.async.cg.shared.global [%0], [%1], 16;" :: "r"(d), "l"(src));
}
#define CP_COMMIT() asm volatile("cp.async.commit_group;")
#define CP_WAIT0()  asm volatile("cp.async.wait_group 0;")
#define CP_WAIT1()  asm volatile("cp.async.wait_group 1;")

// ---------- tf32 mma ----------
__device__ __forceinline__ void mma_tf32(float* d, uint32 a0, uint32 a1,
                                         uint32 a2, uint32 a3,
                                         uint32 b0, uint32 b1) {
    asm volatile(
        "mma.sync.aligned.m16n8k8.row.col.f32.tf32.tf32.f32 "
        "{%0,%1,%2,%3}, {%4,%5,%6,%7}, {%8,%9}, {%0,%1,%2,%3};"
        : "+f"(d[0]), "+f"(d[1]), "+f"(d[2]), "+f"(d[3])
        : "r"(a0), "r"(a1), "r"(a2), "r"(a3), "r"(b0), "r"(b1));
}
__device__ __forceinline__ uint32 fbits(float x) {
    uint32 r; asm("mov.b32 %0, %1;" : "=r"(r) : "f"(x)); return r;
}

// ---------- warp reductions ----------
__device__ __forceinline__ float wmax(float v) {
    #pragma unroll
    for (int o = 16; o > 0; o >>= 1)
        v = fmaxf(v, __shfl_xor_sync(0xffffffffu, v, o));
    return v;
}
__device__ __forceinline__ float wsum(float v) {
    #pragma unroll
    for (int o = 16; o > 0; o >>= 1)
        v += __shfl_xor_sync(0xffffffffu, v, o);
    return v;
}

// =====================================================================
// Kernel 1: conv 1x1 + BN + SiLU  ->  g_f[n][c][hw]  (R10 version)
// =====================================================================
__global__ void __launch_bounds__(256)
conv_kernel(const float* __restrict__ feat,
            const float* __restrict__ convw,
            const float* __restrict__ gamma,
            const float* __restrict__ beta,
            const float* __restrict__ mean,
            const float* __restrict__ var)
{
    const int n  = blockIdx.y;
    const int cb = blockIdx.x * 64;
    const int t  = threadIdx.x;
    const int cs  = t & 31;
    const int csl = t >> 5;

    __shared__ __align__(16) float sW[32 * 64];
    __shared__ __align__(16) float sF[2][32 * 64];

    ull acc[4][2];
    #pragma unroll
    for (int i = 0; i < 4; i++) { acc[i][0] = 0ull; acc[i][1] = 0ull; }

    const int stc = t >> 2;
    const int stq = t & 3;
    const float* wsrc = convw + (size_t)(cb + stc) * CIN + stq * 8;
    const float* fsrc = feat + (size_t)n * CIN * HWs;

    float4 R0 = __ldg((const float4*)(wsrc + 0));
    float4 R1 = __ldg((const float4*)(wsrc + 4));

    #pragma unroll
    for (int i = 0; i < 2; i++)
        cp16(&sF[0][(t + 256 * i) * 4], fsrc + (t + 256 * i) * 4);
    CP_COMMIT();

    int buf = 0;
    const int NCH = CIN / 32;
    for (int ch = 0; ch < NCH; ch++) {
        const int kb = ch * 32;
        {
            int k0 = stq * 8;
            sW[(k0 + 0) * 64 + stc] = R0.x;
            sW[(k0 + 1) * 64 + stc] = R0.y;
            sW[(k0 + 2) * 64 + stc] = R0.z;
            sW[(k0 + 3) * 64 + stc] = R0.w;
            sW[(k0 + 4) * 64 + stc] = R1.x;
            sW[(k0 + 5) * 64 + stc] = R1.y;
            sW[(k0 + 6) * 64 + stc] = R1.z;
            sW[(k0 + 7) * 64 + stc] = R1.w;
        }
        if (ch + 1 < NCH) {
            const float* fs = fsrc + (kb + 32) * HWs;
            #pragma unroll
            for (int i = 0; i < 2; i++)
                cp16(&sF[buf ^ 1][(t + 256 * i) * 4], fs + (t + 256 * i) * 4);
            CP_COMMIT();
            CP_WAIT1();
        } else {
            CP_WAIT0();
        }
        __syncthreads();
        if (ch + 1 < NCH) {
            R0 = __ldg((const float4*)(wsrc + (kb + 32) + 0));
            R1 = __ldg((const float4*)(wsrc + (kb + 32) + 4));
        }
        const float* sfb = &sF[buf][cs * 2];
        #pragma unroll 8
        for (int kk = 0; kk < 32; kk++) {
            float2 bv = *(const float2*)(sfb + kk * 64);
            ull s0 = splat2(bv.x);
            ull s1 = splat2(bv.y);
            const float* wr = sW + kk * 64 + csl * 8;
            ulonglong2 w01 = *(const ulonglong2*)(wr);
            ulonglong2 w23 = *(const ulonglong2*)(wr + 4);
            fma2(acc[0][0], w01.x, s0); fma2(acc[0][1], w01.x, s1);
            fma2(acc[1][0], w01.y, s0); fma2(acc[1][1], w01.y, s1);
            fma2(acc[2][0], w23.x, s0); fma2(acc[2][1], w23.x, s1);
            fma2(acc[3][0], w23.y, s0); fma2(acc[3][1], w23.y, s1);
        }
        __syncthreads();
        buf ^= 1;
    }

    #pragma unroll
    for (int i2 = 0; i2 < 4; i2++) {
        int c0 = cb + csl * 8 + 2 * i2;
        float sc0 = __ldg(gamma + c0) * rsqrtf(__ldg(var + c0) + BN_EPS);
        float bi0 = __ldg(beta + c0) - __ldg(mean + c0) * sc0;
        float sc1 = __ldg(gamma + c0 + 1) * rsqrtf(__ldg(var + c0 + 1) + BN_EPS);
        float bi1 = __ldg(beta + c0 + 1) - __ldg(mean + c0 + 1) * sc1;
        float2 v0 = unpack2(acc[i2][0]);
        float2 v1 = unpack2(acc[i2][1]);
        float a00 = v0.x * sc0 + bi0;  a00 = a00 / (1.0f + __expf(-a00));
        float a01 = v1.x * sc0 + bi0;  a01 = a01 / (1.0f + __expf(-a01));
        float a10 = v0.y * sc1 + bi1;  a10 = a10 / (1.0f + __expf(-a10));
        float a11 = v1.y * sc1 + bi1;  a11 = a11 / (1.0f + __expf(-a11));
        float2* o0 = (float2*)(g_f + ((size_t)n * Cc + c0) * HWs + cs * 2);
        float2* o1 = (float2*)(g_f + ((size_t)n * Cc + c0 + 1) * HWs + cs * 2);
        *o0 = make_float2(a00, a01);
        *o1 = make_float2(a10, a11);
    }
}

// =====================================================================
// Kernel 2: head via tf32 mma.sync, SMALL blocks for overlap
// grid (109, 16) = 1744 blocks, 160 threads = 5 warps, 8 p per block.
// M = 80 rows (row = pl*10 + j), warp w owns m16 tile w (w=0..4).
// N = 64 hw, K = 512 (16 chunks of 32, double-buffered).
// A smem: [pl][k][j], 12 floats/k-row, 388 floats/pl (conflict-free).
// B smem: [k][hw] stride 72 (conflict-free fragment loads).
// 4 blocks/SM -> 4 independent load/compute pipelines per SM.
// =====================================================================
#define PT8   8
#define NPT   109               // ceil(866/8)
#define KC    32
#define NKCH  16
#define SA_F  3104               // 8 * 388
#define SF_F  (KC * 72)          // 2304
#define SMEMH_BYTES ((2 * SA_F + 2 * SF_F) * 4)   // 43264

__global__ void __launch_bounds__(160, 4)
head_mma_kernel(const float* __restrict__ weights, float* __restrict__ out)
{
    const int n    = blockIdx.y;
    const int p0   = blockIdx.x * PT8;
    const int t    = threadIdx.x;
    const int warp = t >> 5;        // 0..4
    const int lane = t & 31;
    const int r4   = lane >> 2;     // 0..7
    const int c4   = lane & 3;      // 0..3

    extern __shared__ __align__(16) float smem[];
    // layout: sA0 [0,3104) sA1 [3104,6208) sF0 [6208,8512) sF1 [8512,10816)

    const uint32 sbase = (uint32)__cvta_generic_to_shared(smem);
    const uint32 sAbytes = SA_F * 4;
    const uint32 fbase0  = sbase + 2 * sAbytes;
    const float* gfn = g_f + (size_t)n * Cc * HWs;

    // ---- A staging: 8 pl x 160 f2 per chunk = 1280 cp8 / 160 thr = 8 each ----
    const float2* srcA[8];
    uint32 dstA[8];
    #pragma unroll
    for (int i = 0; i < 8; i++) {
        int idx = t + 160 * i;                 // 0..1279
        int pl  = idx / 160;
        int r   = idx - pl * 160;
        int p   = p0 + pl; if (p >= Pp) p = Pp - 1;
        srcA[i] = (const float2*)(weights + (size_t)(n * Pp + p) * PW) + r;
        dstA[i] = sbase + (uint32)(pl * 194 + r + r / 5) * 8;
    }

    // ---- prologue: chunk 0 ----
    {
        #pragma unroll
        for (int i = 0; i < 8; i++)
            asm volatile("cp.async.ca.shared.global [%0], [%1], 8;"
                         :: "r"(dstA[i]), "l"(srcA[i]) : "memory");
        #pragma unroll
        for (int i = 0; i < 4; i++) {
            int idx = t + 160 * i;
            if (idx < 512) {
                int k = idx >> 4, off = idx & 15;
                uint32 d = fbase0 + (uint32)(k * 72 + off * 4) * 4;
                asm volatile("cp.async.cg.shared.global [%0], [%1], 16;"
                             :: "r"(d), "l"(gfn + k * 64 + off * 4) : "memory");
            }
        }
        CP_COMMIT();
    }

    // ---- A frag base offsets (float indices) ----
    const int m_lo = warp * 16 + r4;
    const int m_hi = m_lo + 8;
    const int pl_lo = m_lo / 10, j_lo = m_lo - pl_lo * 10;
    const int pl_hi = m_hi / 10, j_hi = m_hi - pl_hi * 10;
    const int aoff_lo = pl_lo * 388 + j_lo + c4 * 12;
    const int aoff_hi = pl_hi * 388 + j_hi + c4 * 12;
    const int boff = c4 * 72 + r4;

    float d[8][4];
    #pragma unroll
    for (int tt = 0; tt < 8; tt++)
        #pragma unroll
        for (int k = 0; k < 4; k++) d[tt][k] = 0.0f;

    int buf = 0;
    for (int ch = 0; ch < NKCH; ch++) {
        if (ch + 1 < NKCH) {
            const uint32 abytes = (buf ^ 1) ? sAbytes : 0u;
            #pragma unroll
            for (int i = 0; i < 8; i++) {
                uint32 dd = dstA[i] + abytes;
                asm volatile("cp.async.ca.shared.global [%0], [%1], 8;"
                             :: "r"(dd), "l"(srcA[i] + (ch + 1) * 160) : "memory");
            }
            const float* fs = gfn + (ch + 1) * (KC * 64);
            const uint32 fb = fbase0 + (buf ^ 1) * (SF_F * 4);
            #pragma unroll
            for (int i = 0; i < 4; i++) {
                int idx = t + 160 * i;
                if (idx < 512) {
                    int k = idx >> 4, off = idx & 15;
                    uint32 dd = fb + (uint32)(k * 72 + off * 4) * 4;
                    asm volatile("cp.async.cg.shared.global [%0], [%1], 16;"
                                 :: "r"(dd), "l"(fs + k * 64 + off * 4) : "memory");
                }
            }
            CP_COMMIT();
            CP_WAIT1();
        } else {
            CP_WAIT0();
        }
        __syncthreads();

        const float* A = smem + buf * SA_F;
        const float* B = smem + 2 * SA_F + buf * SF_F;
        #pragma unroll
        for (int s = 0; s < 4; s++) {
            uint32 a0 = fbits(A[aoff_lo + s * 96]);
            uint32 a1 = fbits(A[aoff_hi + s * 96]);
            uint32 a2 = fbits(A[aoff_lo + s * 96 + 48]);
            uint32 a3 = fbits(A[aoff_hi + s * 96 + 48]);
            const float* Bs = B + s * 576 + boff;
            #pragma unroll
            for (int tt = 0; tt < 8; tt++) {
                uint32 b0 = fbits(Bs[tt * 8]);
                uint32 b1 = fbits(Bs[tt * 8 + 288]);
                mma_tf32(d[tt], a0, a1, a2, a3, b0, b1);
            }
        }
        __syncthreads();
        buf ^= 1;
    }

    // ---- dump logits to smem: L[m][hw], stride 68 (80 rows, 21.8 KB) ----
    float* L = smem;
    #pragma unroll
    for (int tt = 0; tt < 8; tt++) {
        int col = tt * 8 + c4 * 2;
        *(float2*)(L + m_lo * 68 + col) = make_float2(d[tt][0], d[tt][1]);
        *(float2*)(L + m_hi * 68 + col) = make_float2(d[tt][2], d[tt][3]);
    }
    __syncthreads();

    // ---- epilogue: warps 0..3, each handles pl = warp and warp+4 ----
    if (warp < 4) {
        const float inv7 = 1.0f / 7.0f;
        const int hw0 = lane * 2;
        const float x0 = (float)(hw0 & 7) * inv7;
        const float x1 = (float)((hw0 + 1) & 7) * inv7;
        const float yv = (float)(hw0 >> 3) * inv7;

        #pragma unroll
        for (int rep = 0; rep < 2; rep++) {
            const int pl = warp + rep * 4;
            const int pv = p0 + pl;
            const int p  = (pv < Pp) ? pv : (Pp - 1);

            float bias = 0.0f;
            if (lane < 10)
                bias = __ldg(weights + (size_t)(n * Pp + p) * PW + Cc * NOUT + lane);

            float l[10][2];
            #pragma unroll
            for (int j = 0; j < 10; j++) {
                float2 v = *(const float2*)(L + (pl * 10 + j) * 68 + hw0);
                float bj = __shfl_sync(0xffffffffu, bias, j);
                l[j][0] = v.x + bj;
                l[j][1] = v.y + bj;
            }

            // xy softmax (channel 1)
            float mx = wmax(fmaxf(l[1][0], l[1][1]));
            float e0 = __expf(l[1][0] - mx);
            float e1 = __expf(l[1][1] - mx);
            float s  = wsum(e0 + e1);
            float sx = wsum(e0 * x0 + e1 * x1);
            float sy = wsum((e0 + e1) * yv);
            float cx = sx / s;
            float cy = sy / s;

            // 2.5D softmax (channels 2..9)
            float m2 = -INFINITY;
            #pragma unroll
            for (int j = 2; j < 10; j++)
                m2 = fmaxf(m2, fmaxf(l[j][0], l[j][1]));
            m2 = wmax(m2);

            float se = 0.0f, sx2 = 0.0f, sy2 = 0.0f, sz = 0.0f, su = 0.0f;
            #pragma unroll
            for (int j = 2; j < 10; j++) {
                float ea = __expf(l[j][0] - m2);
                float eb = __expf(l[j][1] - m2);
                float zs = (float)(j - 2) * inv7;
                se  += ea + eb;
                sx2 += ea * x0 + eb * x1;
                sy2 += (ea + eb) * yv;
                sz  += (ea + eb) * zs;
                su  += ea * l[0][0] + eb * l[0][1];
            }
            se  = wsum(se);
            sx2 = wsum(sx2);
            sy2 = wsum(sy2);
            sz  = wsum(sz);
            su  = wsum(su);

            if (lane == 0 && pv < Pp) {
                float X = sx2 / se, Y = sy2 / se, Z = sz / se, U = su / se;
                float up = fmaxf(U, 0.0f) + log1pf(__expf(-fabsf(U)));
                int gp = n * Pp + pv;
                out[gp * 2 + 0] = X;
                out[gp * 2 + 1] = Y;
                out[Nn * Pp * 2 + gp * 3 + 0] = cx;
                out[Nn * Pp * 2 + gp * 3 + 1] = cy;
                out[Nn * Pp * 2 + gp * 3 + 2] = Z;
                out[Nn * Pp * 5 + gp] = up;
            }
        }
    }
}

// =====================================================================
extern "C" void kernel_launch(void* const* d_in, const int* in_sizes, int n_in,
                              void* d_out, int out_size)
{
    const float* features = (const float*)d_in[0];
    const float* weights  = (const float*)d_in[1];
    const float* conv_w   = (const float*)d_in[2];
    const float* gamma    = (const float*)d_in[3];
    const float* beta     = (const float*)d_in[4];
    const float* mean     = (const float*)d_in[5];
    const float* var      = (const float*)d_in[6];
    float* out = (float*)d_out;

    conv_kernel<<<dim3(8, Nn), 256>>>(features, conv_w, gamma, beta, mean, var);

    cudaFuncSetAttribute(head_mma_kernel,
                         cudaFuncAttributeMaxDynamicSharedMemorySize,
                         SMEMH_BYTES);
    head_mma_kernel<<<dim3(NPT, Nn), 160, SMEMH_BYTES>>>(weights, out);
}

// round 13
// speedup vs baseline: 1.3649x; 1.1777x over previous
#include <cuda_runtime.h>
#include <math.h>
#include <stdint.h>

#define Nn   16
#define Pp   866
#define CIN  1280
#define Cc   512
#define HWs  64
#define NOUT 10
#define PW   5130          // (Cc+1)*NOUT
#define BN_EPS 0.001f

typedef unsigned long long ull;
typedef unsigned int uint32;

__device__ __align__(16) float g_f[Nn * Cc * HWs];

// ---------- helpers ----------
__device__ __forceinline__ void cp16(void* dst, const void* src) {
    uint32 d = (uint32)__cvta_generic_to_shared(dst);
    asm volatile("cp.async.cg.shared.global [%0], [%1], 16;" :: "r"(d), "l"(src));
}
#define CP_COMMIT() asm volatile("cp.async.commit_group;")
#define CP_WAIT0()  asm volatile("cp.async.wait_group 0;")
#define CP_WAIT1()  asm volatile("cp.async.wait_group 1;")

__device__ __forceinline__ void mma_tf32(float* d, uint32 a0, uint32 a1,
                                         uint32 a2, uint32 a3,
                                         uint32 b0, uint32 b1) {
    asm volatile(
        "mma.sync.aligned.m16n8k8.row.col.f32.tf32.tf32.f32 "
        "{%0,%1,%2,%3}, {%4,%5,%6,%7}, {%8,%9}, {%0,%1,%2,%3};"
        : "+f"(d[0]), "+f"(d[1]), "+f"(d[2]), "+f"(d[3])
        : "r"(a0), "r"(a1), "r"(a2), "r"(a3), "r"(b0), "r"(b1));
}
__device__ __forceinline__ uint32 fbits(float x) {
    uint32 r; asm("mov.b32 %0, %1;" : "=r"(r) : "f"(x)); return r;
}

__device__ __forceinline__ float wmax(float v) {
    #pragma unroll
    for (int o = 16; o > 0; o >>= 1)
        v = fmaxf(v, __shfl_xor_sync(0xffffffffu, v, o));
    return v;
}
__device__ __forceinline__ float wsum(float v) {
    #pragma unroll
    for (int o = 16; o > 0; o >>= 1)
        v += __shfl_xor_sync(0xffffffffu, v, o);
    return v;
}

// =====================================================================
// Kernel 1: conv 1x1 + BN + SiLU via tf32 mma.sync
// grid (8 ctiles of 64c, 16 n), 256 threads = 8 warps.
// M=64 (4 m16 tiles), N=64 hw, K=1280 (40 chunks of 32, double-buffered).
// warp w: tile = w&3, khalf = w>>2 (k-split x2, combined via smem).
// A smem [c][k] pad 36; B smem [k][hw] pad 72 (both conflict-free).
// =====================================================================
#define CNCH  40
#define CW_F  2304               // 64 * 36
#define CB_F  2304               // 32 * 72
#define CSTG  (CW_F + CB_F)      // 4608 floats per buffer

__global__ void __launch_bounds__(256)
conv_kernel(const float* __restrict__ feat,
            const float* __restrict__ convw,
            const float* __restrict__ gamma,
            const float* __restrict__ beta,
            const float* __restrict__ mean,
            const float* __restrict__ var)
{
    const int n  = blockIdx.y;
    const int cb = blockIdx.x * 64;
    const int t  = threadIdx.x;
    const int warp = t >> 5;
    const int lane = t & 31;
    const int r4 = lane >> 2;
    const int c4 = lane & 3;
    const int tile  = warp & 3;
    const int khalf = warp >> 2;

    __shared__ __align__(16) float smem[2 * CSTG];   // 36864 B

    const float* fsrc = feat + (size_t)n * CIN * HWs;   // [k][hw]
    const float* wsrc = convw + (size_t)cb * CIN;        // [c][k]

    // staging maps
    const int sc = t >> 2;            // A: c 0..63
    const int sq = t & 3;             // A: k-octet 0..3 (8 k each, 2 cp16)
    // B: idx = t (+256): k = idx>>4, off = idx&15

    // ---- prologue: chunk 0 ----
    {
        float* W0 = smem;
        float* B0 = smem + CW_F;
        #pragma unroll
        for (int i = 0; i < 2; i++)
            cp16(W0 + sc * 36 + sq * 8 + 4 * i, wsrc + (size_t)sc * CIN + sq * 8 + 4 * i);
        #pragma unroll
        for (int i = 0; i < 2; i++) {
            int idx = t + 256 * i;
            int k = idx >> 4, off = idx & 15;
            cp16(B0 + k * 72 + off * 4, fsrc + k * 64 + off * 4);
        }
        CP_COMMIT();
    }

    float d[8][4];
    #pragma unroll
    for (int tt = 0; tt < 8; tt++)
        #pragma unroll
        for (int q = 0; q < 4; q++) d[tt][q] = 0.0f;

    const int arow_lo = (tile * 16 + r4) * 36;
    const int arow_hi = (tile * 16 + r4 + 8) * 36;
    const int kbase = khalf * 16;

    int buf = 0;
    for (int ch = 0; ch < CNCH; ch++) {
        if (ch + 1 < CNCH) {
            float* Wn = smem + (buf ^ 1) * CSTG;
            float* Bn = Wn + CW_F;
            const float* ws = wsrc + (ch + 1) * 32;
            const float* fs = fsrc + (ch + 1) * 32 * 64;
            #pragma unroll
            for (int i = 0; i < 2; i++)
                cp16(Wn + sc * 36 + sq * 8 + 4 * i, ws + (size_t)sc * CIN + sq * 8 + 4 * i);
            #pragma unroll
            for (int i = 0; i < 2; i++) {
                int idx = t + 256 * i;
                int k = idx >> 4, off = idx & 15;
                cp16(Bn + k * 72 + off * 4, fs + k * 64 + off * 4);
            }
            CP_COMMIT();
            CP_WAIT1();
        } else {
            CP_WAIT0();
        }
        __syncthreads();

        const float* W = smem + buf * CSTG;
        const float* B = W + CW_F;
        #pragma unroll
        for (int s = 0; s < 2; s++) {
            const int kl = kbase + s * 8;
            uint32 a0 = fbits(W[arow_lo + kl + c4]);
            uint32 a1 = fbits(W[arow_hi + kl + c4]);
            uint32 a2 = fbits(W[arow_lo + kl + c4 + 4]);
            uint32 a3 = fbits(W[arow_hi + kl + c4 + 4]);
            const float* Bs = B + (kl + c4) * 72 + r4;
            #pragma unroll
            for (int tt = 0; tt < 8; tt++) {
                uint32 b0 = fbits(Bs[tt * 8]);
                uint32 b1 = fbits(Bs[tt * 8 + 288]);
                mma_tf32(d[tt], a0, a1, a2, a3, b0, b1);
            }
        }
        __syncthreads();
        buf ^= 1;
    }

    // ---- combine k-halves via smem (reuse staging region) ----
    float* comb = smem;     // 4 tiles x 16 rows x 68 = 4352 floats
    if (khalf == 1) {
        float* cb_ = comb + tile * 1088;
        #pragma unroll
        for (int tt = 0; tt < 8; tt++) {
            int col = tt * 8 + c4 * 2;
            *(float2*)(cb_ + r4 * 68 + col)       = make_float2(d[tt][0], d[tt][1]);
            *(float2*)(cb_ + (r4 + 8) * 68 + col) = make_float2(d[tt][2], d[tt][3]);
        }
    }
    __syncthreads();

    if (khalf == 0) {
        const float* cb_ = comb + tile * 1088;
        #pragma unroll
        for (int tt = 0; tt < 8; tt++) {
            int col = tt * 8 + c4 * 2;
            float2 v0 = *(const float2*)(cb_ + r4 * 68 + col);
            float2 v1 = *(const float2*)(cb_ + (r4 + 8) * 68 + col);
            d[tt][0] += v0.x; d[tt][1] += v0.y;
            d[tt][2] += v1.x; d[tt][3] += v1.y;
        }

        const int c_lo = cb + tile * 16 + r4;
        const int c_hi = c_lo + 8;
        float sc0 = __ldg(gamma + c_lo) * rsqrtf(__ldg(var + c_lo) + BN_EPS);
        float bi0 = __ldg(beta + c_lo) - __ldg(mean + c_lo) * sc0;
        float sc1 = __ldg(gamma + c_hi) * rsqrtf(__ldg(var + c_hi) + BN_EPS);
        float bi1 = __ldg(beta + c_hi) - __ldg(mean + c_hi) * sc1;

        float* o_lo = g_f + ((size_t)n * Cc + c_lo) * HWs;
        float* o_hi = g_f + ((size_t)n * Cc + c_hi) * HWs;
        #pragma unroll
        for (int tt = 0; tt < 8; tt++) {
            int col = tt * 8 + c4 * 2;
            float a0 = d[tt][0] * sc0 + bi0;  a0 = a0 / (1.0f + __expf(-a0));
            float a1 = d[tt][1] * sc0 + bi0;  a1 = a1 / (1.0f + __expf(-a1));
            float a2 = d[tt][2] * sc1 + bi1;  a2 = a2 / (1.0f + __expf(-a2));
            float a3 = d[tt][3] * sc1 + bi1;  a3 = a3 / (1.0f + __expf(-a3));
            *(float2*)(o_lo + col) = make_float2(a0, a1);
            *(float2*)(o_hi + col) = make_float2(a2, a3);
        }
    }
}

// =====================================================================
// Kernel 2: head via tf32 mma.sync  (R12 winner, unchanged)
// grid (109, 16) = 1744 blocks, 160 threads = 5 warps, 8 p per block.
// =====================================================================
#define PT8   8
#define NPT   109
#define KC    32
#define NKCH  16
#define SA_F  3104               // 8 * 388
#define SF_F  (KC * 72)          // 2304
#define SMEMH_BYTES ((2 * SA_F + 2 * SF_F) * 4)   // 43264

__global__ void __launch_bounds__(160, 4)
head_mma_kernel(const float* __restrict__ weights, float* __restrict__ out)
{
    const int n    = blockIdx.y;
    const int p0   = blockIdx.x * PT8;
    const int t    = threadIdx.x;
    const int warp = t >> 5;
    const int lane = t & 31;
    const int r4   = lane >> 2;
    const int c4   = lane & 3;

    extern __shared__ __align__(16) float smem[];

    const uint32 sbase = (uint32)__cvta_generic_to_shared(smem);
    const uint32 sAbytes = SA_F * 4;
    const uint32 fbase0  = sbase + 2 * sAbytes;
    const float* gfn = g_f + (size_t)n * Cc * HWs;

    const float2* srcA[8];
    uint32 dstA[8];
    #pragma unroll
    for (int i = 0; i < 8; i++) {
        int idx = t + 160 * i;
        int pl  = idx / 160;
        int r   = idx - pl * 160;
        int p   = p0 + pl; if (p >= Pp) p = Pp - 1;
        srcA[i] = (const float2*)(weights + (size_t)(n * Pp + p) * PW) + r;
        dstA[i] = sbase + (uint32)(pl * 194 + r + r / 5) * 8;
    }

    {
        #pragma unroll
        for (int i = 0; i < 8; i++)
            asm volatile("cp.async.ca.shared.global [%0], [%1], 8;"
                         :: "r"(dstA[i]), "l"(srcA[i]) : "memory");
        #pragma unroll
        for (int i = 0; i < 4; i++) {
            int idx = t + 160 * i;
            if (idx < 512) {
                int k = idx >> 4, off = idx & 15;
                uint32 d = fbase0 + (uint32)(k * 72 + off * 4) * 4;
                asm volatile("cp.async.cg.shared.global [%0], [%1], 16;"
                             :: "r"(d), "l"(gfn + k * 64 + off * 4) : "memory");
            }
        }
        CP_COMMIT();
    }

    const int m_lo = warp * 16 + r4;
    const int m_hi = m_lo + 8;
    const int pl_lo = m_lo / 10, j_lo = m_lo - pl_lo * 10;
    const int pl_hi = m_hi / 10, j_hi = m_hi - pl_hi * 10;
    const int aoff_lo = pl_lo * 388 + j_lo + c4 * 12;
    const int aoff_hi = pl_hi * 388 + j_hi + c4 * 12;
    const int boff = c4 * 72 + r4;

    float d[8][4];
    #pragma unroll
    for (int tt = 0; tt < 8; tt++)
        #pragma unroll
        for (int k = 0; k < 4; k++) d[tt][k] = 0.0f;

    int buf = 0;
    for (int ch = 0; ch < NKCH; ch++) {
        if (ch + 1 < NKCH) {
            const uint32 abytes = (buf ^ 1) ? sAbytes : 0u;
            #pragma unroll
            for (int i = 0; i < 8; i++) {
                uint32 dd = dstA[i] + abytes;
                asm volatile("cp.async.ca.shared.global [%0], [%1], 8;"
                             :: "r"(dd), "l"(srcA[i] + (ch + 1) * 160) : "memory");
            }
            const float* fs = gfn + (ch + 1) * (KC * 64);
            const uint32 fb = fbase0 + (buf ^ 1) * (SF_F * 4);
            #pragma unroll
            for (int i = 0; i < 4; i++) {
                int idx = t + 160 * i;
                if (idx < 512) {
                    int k = idx >> 4, off = idx & 15;
                    uint32 dd = fb + (uint32)(k * 72 + off * 4) * 4;
                    asm volatile("cp.async.cg.shared.global [%0], [%1], 16;"
                                 :: "r"(dd), "l"(fs + k * 64 + off * 4) : "memory");
                }
            }
            CP_COMMIT();
            CP_WAIT1();
        } else {
            CP_WAIT0();
        }
        __syncthreads();

        const float* A = smem + buf * SA_F;
        const float* B = smem + 2 * SA_F + buf * SF_F;
        #pragma unroll
        for (int s = 0; s < 4; s++) {
            uint32 a0 = fbits(A[aoff_lo + s * 96]);
            uint32 a1 = fbits(A[aoff_hi + s * 96]);
            uint32 a2 = fbits(A[aoff_lo + s * 96 + 48]);
            uint32 a3 = fbits(A[aoff_hi + s * 96 + 48]);
            const float* Bs = B + s * 576 + boff;
            #pragma unroll
            for (int tt = 0; tt < 8; tt++) {
                uint32 b0 = fbits(Bs[tt * 8]);
                uint32 b1 = fbits(Bs[tt * 8 + 288]);
                mma_tf32(d[tt], a0, a1, a2, a3, b0, b1);
            }
        }
        __syncthreads();
        buf ^= 1;
    }

    float* L = smem;
    #pragma unroll
    for (int tt = 0; tt < 8; tt++) {
        int col = tt * 8 + c4 * 2;
        *(float2*)(L + m_lo * 68 + col) = make_float2(d[tt][0], d[tt][1]);
        *(float2*)(L + m_hi * 68 + col) = make_float2(d[tt][2], d[tt][3]);
    }
    __syncthreads();

    if (warp < 4) {
        const float inv7 = 1.0f / 7.0f;
        const int hw0 = lane * 2;
        const float x0 = (float)(hw0 & 7) * inv7;
        const float x1 = (float)((hw0 + 1) & 7) * inv7;
        const float yv = (float)(hw0 >> 3) * inv7;

        #pragma unroll
        for (int rep = 0; rep < 2; rep++) {
            const int pl = warp + rep * 4;
            const int pv = p0 + pl;
            const int p  = (pv < Pp) ? pv : (Pp - 1);

            float bias = 0.0f;
            if (lane < 10)
                bias = __ldg(weights + (size_t)(n * Pp + p) * PW + Cc * NOUT + lane);

            float l[10][2];
            #pragma unroll
            for (int j = 0; j < 10; j++) {
                float2 v = *(const float2*)(L + (pl * 10 + j) * 68 + hw0);
                float bj = __shfl_sync(0xffffffffu, bias, j);
                l[j][0] = v.x + bj;
                l[j][1] = v.y + bj;
            }

            float mx = wmax(fmaxf(l[1][0], l[1][1]));
            float e0 = __expf(l[1][0] - mx);
            float e1 = __expf(l[1][1] - mx);
            float s  = wsum(e0 + e1);
            float sx = wsum(e0 * x0 + e1 * x1);
            float sy = wsum((e0 + e1) * yv);
            float cx = sx / s;
            float cy = sy / s;

            float m2 = -INFINITY;
            #pragma unroll
            for (int j = 2; j < 10; j++)
                m2 = fmaxf(m2, fmaxf(l[j][0], l[j][1]));
            m2 = wmax(m2);

            float se = 0.0f, sx2 = 0.0f, sy2 = 0.0f, sz = 0.0f, su = 0.0f;
            #pragma unroll
            for (int j = 2; j < 10; j++) {
                float ea = __expf(l[j][0] - m2);
                float eb = __expf(l[j][1] - m2);
                float zs = (float)(j - 2) * inv7;
                se  += ea + eb;
                sx2 += ea * x0 + eb * x1;
                sy2 += (ea + eb) * yv;
                sz  += (ea + eb) * zs;
                su  += ea * l[0][0] + eb * l[0][1];
            }
            se  = wsum(se);
            sx2 = wsum(sx2);
            sy2 = wsum(sy2);
            sz  = wsum(sz);
            su  = wsum(su);

            if (lane == 0 && pv < Pp) {
                float X = sx2 / se, Y = sy2 / se, Z = sz / se, U = su / se;
                float up = fmaxf(U, 0.0f) + log1pf(__expf(-fabsf(U)));
                int gp = n * Pp + pv;
                out[gp * 2 + 0] = X;
                out[gp * 2 + 1] = Y;
                out[Nn * Pp * 2 + gp * 3 + 0] = cx;
                out[Nn * Pp * 2 + gp * 3 + 1] = cy;
                out[Nn * Pp * 2 + gp * 3 + 2] = Z;
                out[Nn * Pp * 5 + gp] = up;
            }
        }
    }
}

// =====================================================================
extern "C" void kernel_launch(void* const* d_in, const int* in_sizes, int n_in,
                              void* d_out, int out_size)
{
    const float* features = (const float*)d_in[0];
    const float* weights  = (const float*)d_in[1];
    const float* conv_w   = (const float*)d_in[2];
    const float* gamma    = (const float*)d_in[3];
    const float* beta     = (const float*)d_in[4];
    const float* mean     = (const float*)d_in[5];
    const float* var      = (const float*)d_in[6];
    float* out = (float*)d_out;

    conv_kernel<<<dim3(8, Nn), 256>>>(features, conv_w, gamma, beta, mean, var);

    cudaFuncSetAttribute(head_mma_kernel,
                         cudaFuncAttributeMaxDynamicSharedMemorySize,
                         SMEMH_BYTES);
    head_mma_kernel<<<dim3(NPT, Nn), 160, SMEMH_BYTES>>>(weights, out);
}